// round 1
// baseline (speedup 1.0000x reference)
#include <cuda_runtime.h>
#include <cuda_bf16.h>
#include <math_constants.h>

// Problem constants
#define BATCH  2
#define SEQ    2048
#define DMODEL 1024
#define NHEAD  16
#define HDIM   64            // DK
#define MTOT   (BATCH*SEQ)   // 4096

// -------- scratch (device globals; no allocation allowed) --------
__device__ float g_Q[BATCH*NHEAD*SEQ*HDIM];   // [B,H,S,DK]
__device__ float g_K[BATCH*NHEAD*SEQ*HDIM];
__device__ float g_V[BATCH*NHEAD*SEQ*HDIM];
__device__ float g_O[BATCH*SEQ*DMODEL];       // attention out, combined heads [B,S,D]

// ============================================================================
// Projection GEMM: Y[m,n] = sum_k X[m,k] * W[n,k] + bias[n]
// M=4096, N=1024, K=1024.  BM=BN=64, BK=16, 256 threads, 4x4 per thread.
// HEADED: write to [B,H,S,DK] layout; else plain row-major [M,N].
// ============================================================================
template<bool HEADED>
__global__ __launch_bounds__(256)
void gemm_proj(const float* __restrict__ X, const float* __restrict__ W,
               const float* __restrict__ bias, float* __restrict__ Y)
{
    __shared__ float As[64][17];   // [m][k], padded
    __shared__ float Bs[64][17];   // [n][k], padded

    const int tid = threadIdx.x;
    const int tx  = tid & 15;      // n group
    const int ty  = tid >> 4;      // m group
    const int n0  = blockIdx.x * 64;
    const int m0  = blockIdx.y * 64;

    const int lrow = tid >> 2;     // 0..63
    const int lc4  = tid & 3;      // 0..3 (float4 within 16-wide k chunk)

    float acc[4][4];
#pragma unroll
    for (int i = 0; i < 4; i++)
#pragma unroll
        for (int j = 0; j < 4; j++) acc[i][j] = 0.f;

    for (int k0 = 0; k0 < DMODEL; k0 += 16) {
        float4 av = *(const float4*)(X + (size_t)(m0 + lrow) * DMODEL + k0 + lc4 * 4);
        float4 bv = *(const float4*)(W + (size_t)(n0 + lrow) * DMODEL + k0 + lc4 * 4);
        As[lrow][lc4*4+0] = av.x; As[lrow][lc4*4+1] = av.y;
        As[lrow][lc4*4+2] = av.z; As[lrow][lc4*4+3] = av.w;
        Bs[lrow][lc4*4+0] = bv.x; Bs[lrow][lc4*4+1] = bv.y;
        Bs[lrow][lc4*4+2] = bv.z; Bs[lrow][lc4*4+3] = bv.w;
        __syncthreads();

#pragma unroll
        for (int kk = 0; kk < 16; kk++) {
            float a[4], b[4];
#pragma unroll
            for (int i = 0; i < 4; i++) a[i] = As[ty*4+i][kk];
#pragma unroll
            for (int j = 0; j < 4; j++) b[j] = Bs[tx*4+j][kk];
#pragma unroll
            for (int i = 0; i < 4; i++)
#pragma unroll
                for (int j = 0; j < 4; j++)
                    acc[i][j] += a[i] * b[j];
        }
        __syncthreads();
    }

#pragma unroll
    for (int i = 0; i < 4; i++) {
        const int m = m0 + ty*4 + i;
#pragma unroll
        for (int j = 0; j < 4; j++) {
            const int n = n0 + tx*4 + j;
            const float val = acc[i][j] + bias[n];
            if (HEADED) {
                const int b  = m >> 11;          // /SEQ
                const int s  = m & (SEQ-1);
                const int h  = n >> 6;           // /HDIM
                const int dk = n & (HDIM-1);
                g_dummy_noop: ;
                // index into [B,H,S,DK]
                Y[(((size_t)(b*NHEAD + h))*SEQ + s)*HDIM + dk] = val;
            } else {
                Y[(size_t)m * DMODEL + n] = val;
            }
        }
    }
}

// ============================================================================
// Causal flash attention over head-split fp32 Q/K/V.
// Block: 64 q-rows of one (b,h). 256 threads (16x16), 4x4 tiles.
// Smem: Qs [64][64], Ks [64][65] (aliased as P after scores), Vs [64][65].
// ============================================================================
#define FLASH_SMEM ((64*64 + 64*65 + 64*65) * 4)

__global__ __launch_bounds__(256)
void flash_attn(const float* __restrict__ gQ, const float* __restrict__ gK,
                const float* __restrict__ gV, float* __restrict__ gO)
{
    extern __shared__ float sm[];
    float* Qs = sm;                 // [64][64]
    float* Ks = sm + 64*64;         // [64][65]  (reused as P)
    float* Vs = Ks + 64*65;         // [64][65]

    const int tid = threadIdx.x;
    const int tx  = tid & 15;       // dk / kcol group
    const int ty  = tid >> 4;       // qrow group
    const int qt  = blockIdx.x;     // q tile (0..31)
    const int bh  = blockIdx.y;     // 0..31
    const int bb  = bh >> 4;
    const int hh  = bh & 15;

    const float* Qbase = gQ + (size_t)bh * SEQ * HDIM + (size_t)qt * 64 * HDIM;
    const float* Kbh   = gK + (size_t)bh * SEQ * HDIM;
    const float* Vbh   = gV + (size_t)bh * SEQ * HDIM;

    // load Q tile (row-major, float4, conflict-free)
#pragma unroll
    for (int it = 0; it < 4; it++) {
        const int idx = tid + it * 256;       // 0..1023
        const int row = idx >> 4;
        const int c4  = idx & 15;
        *(float4*)(Qs + row*64 + c4*4) = *(const float4*)(Qbase + row*64 + c4*4);
    }

    float m_i[4], l_i[4], acc[4][4];
#pragma unroll
    for (int i = 0; i < 4; i++) {
        m_i[i] = -CUDART_INF_F;
        l_i[i] = 0.f;
#pragma unroll
        for (int j = 0; j < 4; j++) acc[i][j] = 0.f;
    }

    for (int jt = 0; jt <= qt; jt++) {
        const float* Kb = Kbh + (size_t)jt * 64 * HDIM;
        const float* Vb = Vbh + (size_t)jt * 64 * HDIM;
        __syncthreads();   // protect Ks(P)/Vs from previous iteration readers
#pragma unroll
        for (int it = 0; it < 4; it++) {
            const int idx = tid + it * 256;
            const int row = idx >> 4;
            const int c4  = idx & 15;
            float4 kv = *(const float4*)(Kb + row*64 + c4*4);
            float4 vv = *(const float4*)(Vb + row*64 + c4*4);
            Ks[row*65 + c4*4+0] = kv.x; Ks[row*65 + c4*4+1] = kv.y;
            Ks[row*65 + c4*4+2] = kv.z; Ks[row*65 + c4*4+3] = kv.w;
            Vs[row*65 + c4*4+0] = vv.x; Vs[row*65 + c4*4+1] = vv.y;
            Vs[row*65 + c4*4+2] = vv.z; Vs[row*65 + c4*4+3] = vv.w;
        }
        __syncthreads();

        // scores S = Q K^T * scale  (4x4 per thread)
        float s[4][4];
#pragma unroll
        for (int i = 0; i < 4; i++)
#pragma unroll
            for (int j = 0; j < 4; j++) s[i][j] = 0.f;

#pragma unroll 8
        for (int kk = 0; kk < HDIM; kk++) {
            float a[4], b[4];
#pragma unroll
            for (int i = 0; i < 4; i++) a[i] = Qs[(ty*4+i)*64 + kk];
#pragma unroll
            for (int j = 0; j < 4; j++) b[j] = Ks[(tx*4+j)*65 + kk];
#pragma unroll
            for (int i = 0; i < 4; i++)
#pragma unroll
                for (int j = 0; j < 4; j++)
                    s[i][j] += a[i] * b[j];
        }

        const bool diag = (jt == qt);
#pragma unroll
        for (int i = 0; i < 4; i++)
#pragma unroll
            for (int j = 0; j < 4; j++) {
                s[i][j] *= 0.125f;   // 1/sqrt(64)
                if (diag && (tx*4+j) > (ty*4+i)) s[i][j] = -1e9f;
            }

        __syncthreads();   // everyone done reading Ks before it becomes P

        // online softmax (per q-row; replicated across the 16 tx lanes)
        float p[4][4];
#pragma unroll
        for (int i = 0; i < 4; i++) {
            float t = fmaxf(fmaxf(s[i][0], s[i][1]), fmaxf(s[i][2], s[i][3]));
            t = fmaxf(t, __shfl_xor_sync(0xffffffffu, t, 8));
            t = fmaxf(t, __shfl_xor_sync(0xffffffffu, t, 4));
            t = fmaxf(t, __shfl_xor_sync(0xffffffffu, t, 2));
            t = fmaxf(t, __shfl_xor_sync(0xffffffffu, t, 1));
            const float mnew = fmaxf(m_i[i], t);
            const float corr = __expf(m_i[i] - mnew);
            float rs = 0.f;
#pragma unroll
            for (int j = 0; j < 4; j++) {
                p[i][j] = __expf(s[i][j] - mnew);
                rs += p[i][j];
            }
            rs += __shfl_xor_sync(0xffffffffu, rs, 8);
            rs += __shfl_xor_sync(0xffffffffu, rs, 4);
            rs += __shfl_xor_sync(0xffffffffu, rs, 2);
            rs += __shfl_xor_sync(0xffffffffu, rs, 1);
            l_i[i] = l_i[i] * corr + rs;
            m_i[i] = mnew;
#pragma unroll
            for (int j = 0; j < 4; j++) acc[i][j] *= corr;
            // store P into Ks buffer
#pragma unroll
            for (int j = 0; j < 4; j++)
                Ks[(ty*4+i)*65 + tx*4+j] = p[i][j];
        }
        __syncthreads();

        // acc += P @ V  (P: [64 q x 64 kcol] in Ks, V: [64 kcol x 64 dk])
#pragma unroll 8
        for (int kk = 0; kk < 64; kk++) {
            float a[4], b[4];
#pragma unroll
            for (int i = 0; i < 4; i++) a[i] = Ks[(ty*4+i)*65 + kk];
#pragma unroll
            for (int j = 0; j < 4; j++) b[j] = Vs[kk*65 + tx*4+j];
#pragma unroll
            for (int i = 0; i < 4; i++)
#pragma unroll
                for (int j = 0; j < 4; j++)
                    acc[i][j] += a[i] * b[j];
        }
    }

    // epilogue: normalize, write combined-head layout [B,S,D]
#pragma unroll
    for (int i = 0; i < 4; i++) {
        const float inv = 1.f / l_i[i];
        const int srow = qt*64 + ty*4 + i;
#pragma unroll
        for (int j = 0; j < 4; j++) {
            const int col = hh*64 + tx*4 + j;
            gO[((size_t)(bb*SEQ + srow))*DMODEL + col] = acc[i][j] * inv;
        }
    }
}

// ============================================================================
extern "C" void kernel_launch(void* const* d_in, const int* in_sizes, int n_in,
                              void* d_out, int out_size)
{
    (void)in_sizes; (void)n_in; (void)out_size;
    const float* q  = (const float*)d_in[0];
    const float* k  = (const float*)d_in[1];
    const float* v  = (const float*)d_in[2];
    /* d_in[3] = causal mask (bool), implemented analytically */
    const float* Wq = (const float*)d_in[4];
    const float* bq = (const float*)d_in[5];
    const float* Wk = (const float*)d_in[6];
    const float* bk = (const float*)d_in[7];
    const float* Wv = (const float*)d_in[8];
    const float* bv = (const float*)d_in[9];
    const float* Wo = (const float*)d_in[10];
    const float* bo = (const float*)d_in[11];
    float* out = (float*)d_out;

    float *gQ, *gK, *gV, *gO;
    cudaGetSymbolAddress((void**)&gQ, g_Q);
    cudaGetSymbolAddress((void**)&gK, g_K);
    cudaGetSymbolAddress((void**)&gV, g_V);
    cudaGetSymbolAddress((void**)&gO, g_O);

    cudaFuncSetAttribute(flash_attn, cudaFuncAttributeMaxDynamicSharedMemorySize,
                         FLASH_SMEM);

    const dim3 gridG(DMODEL/64, MTOT/64);   // (16, 64)
    const dim3 tb(256);

    gemm_proj<true><<<gridG, tb>>>(q, Wq, bq, gQ);
    gemm_proj<true><<<gridG, tb>>>(k, Wk, bk, gK);
    gemm_proj<true><<<gridG, tb>>>(v, Wv, bv, gV);

    flash_attn<<<dim3(SEQ/64, BATCH*NHEAD), tb, FLASH_SMEM>>>(gQ, gK, gV, gO);

    gemm_proj<false><<<gridG, tb>>>(gO, Wo, bo, out);
}

// round 3
// speedup vs baseline: 1.6245x; 1.6245x over previous
#include <cuda_runtime.h>
#include <cuda_bf16.h>
#include <math_constants.h>
#include <cstdint>

// Problem constants
#define BATCH  2
#define SEQ    2048
#define DMODEL 1024
#define NHEAD  16
#define HDIM   64
#define MTOT   (BATCH*SEQ)   // 4096

// ---------------- scratch (device globals; no allocation allowed) ----------
__device__ float g_Q[BATCH*NHEAD*SEQ*HDIM];   // [B,H,S,DK]
__device__ float g_K[BATCH*NHEAD*SEQ*HDIM];
__device__ float g_V[BATCH*NHEAD*SEQ*HDIM];
__device__ float g_O[BATCH*SEQ*DMODEL];       // attention out, [B,S,D]

__device__ __align__(16) __nv_bfloat16 g_Xhi[MTOT*DMODEL];
__device__ __align__(16) __nv_bfloat16 g_Xlo[MTOT*DMODEL];
__device__ __align__(16) __nv_bfloat16 g_Whi[DMODEL*DMODEL];
__device__ __align__(16) __nv_bfloat16 g_Wlo[DMODEL*DMODEL];

// ---------------- base-PTX helpers (compute_103-safe) ----------------------
__device__ __forceinline__ uint32_t smem_u32(const void* p) {
    uint32_t a;
    asm("{ .reg .u64 t; cvta.to.shared.u64 t, %1; cvt.u32.u64 %0, t; }"
        : "=r"(a) : "l"(p));
    return a;
}
__device__ __forceinline__ void cp_async16(uint32_t s, const void* g) {
    asm volatile("cp.async.cg.shared.global [%0], [%1], 16;"
                 :: "r"(s), "l"(g) : "memory");
}
#define CP_COMMIT() asm volatile("cp.async.commit_group;" ::: "memory")
#define CP_WAIT(N)  asm volatile("cp.async.wait_group %0;" :: "n"(N) : "memory")

__device__ __forceinline__ void ldsm4(uint32_t (&r)[4], uint32_t a) {
    asm volatile("ldmatrix.sync.aligned.m8n8.x4.shared.b16 {%0,%1,%2,%3}, [%4];"
                 : "=r"(r[0]), "=r"(r[1]), "=r"(r[2]), "=r"(r[3]) : "r"(a));
}
__device__ __forceinline__ void mma16816(float (&d)[4], const uint32_t (&a)[4],
                                         uint32_t b0, uint32_t b1) {
    asm volatile(
        "mma.sync.aligned.m16n8k16.row.col.f32.bf16.bf16.f32 "
        "{%0,%1,%2,%3}, {%4,%5,%6,%7}, {%8,%9}, {%0,%1,%2,%3};"
        : "+f"(d[0]), "+f"(d[1]), "+f"(d[2]), "+f"(d[3])
        : "r"(a[0]), "r"(a[1]), "r"(a[2]), "r"(a[3]), "r"(b0), "r"(b1));
}

// ============================================================================
// Split fp32 -> bf16 hi/lo
// ============================================================================
__global__ __launch_bounds__(256)
void split_bf16(const float* __restrict__ x, __nv_bfloat16* __restrict__ hi,
                __nv_bfloat16* __restrict__ lo, int n4)
{
    int i = blockIdx.x * blockDim.x + threadIdx.x;
    if (i >= n4) return;
    float4 v = ((const float4*)x)[i];
    __nv_bfloat16 h0 = __float2bfloat16(v.x), h1 = __float2bfloat16(v.y);
    __nv_bfloat16 h2 = __float2bfloat16(v.z), h3 = __float2bfloat16(v.w);
    __nv_bfloat162 H0 = __nv_bfloat162(h0, h1), H1 = __nv_bfloat162(h2, h3);
    __nv_bfloat162 L0 = __nv_bfloat162(__float2bfloat16(v.x - __bfloat162float(h0)),
                                       __float2bfloat16(v.y - __bfloat162float(h1)));
    __nv_bfloat162 L1 = __nv_bfloat162(__float2bfloat16(v.z - __bfloat162float(h2)),
                                       __float2bfloat16(v.w - __bfloat162float(h3)));
    ((__nv_bfloat162*)hi)[i*2+0] = H0;  ((__nv_bfloat162*)hi)[i*2+1] = H1;
    ((__nv_bfloat162*)lo)[i*2+0] = L0;  ((__nv_bfloat162*)lo)[i*2+1] = L1;
}

// ============================================================================
// HMMA GEMM: Y[m,n] = sum_k X[m,k]*W[n,k] + bias[n], fp32 via bf16x3.
// M=4096, N=1024, K=1024. CTA 128x128, BK=64, 256 threads (8 warps, 4m x 2n).
// SMEM: 2 stages x 4 tiles (Ahi,Alo,Bhi,Blo), 128 rows x 72 bf16 (144B) each.
// ============================================================================
#define ROWB   144                 // padded row bytes (72 bf16)
#define TILEB  (128*ROWB)          // 18432
#define STAGEB (4*TILEB)           // 73728
#define GEMM_SMEM (2*STAGEB)       // 147456

template<bool HEADED>
__global__ __launch_bounds__(256, 1)
void gemm_tc(const __nv_bfloat16* __restrict__ Ahi, const __nv_bfloat16* __restrict__ Alo,
             const __nv_bfloat16* __restrict__ Bhi, const __nv_bfloat16* __restrict__ Blo,
             const float* __restrict__ bias, float* __restrict__ Y)
{
    extern __shared__ char smem[];
    const uint32_t sb = smem_u32(smem);
    const int tid  = threadIdx.x;
    const int wid  = tid >> 5;
    const int lane = tid & 31;
    const int n0 = blockIdx.x * 128;
    const int m0 = blockIdx.y * 128;
    const int wm = (wid & 3) * 32;    // warp m offset (4 warps over m)
    const int wn = (wid >> 2) * 64;   // warp n offset (2 warps over n)

    // --- async stage loader: 16 cp.async(16B) per thread ---
    auto issue_stage = [&](int ch, int buf) {
        const int k0 = ch * 64;
#pragma unroll
        for (int i = 0; i < 16; i++) {
            const int idx = tid + i * 256;        // 0..4095
            const int mat = idx >> 10;            // 0..3
            const int r   = (idx >> 3) & 127;
            const int c   = idx & 7;
            const __nv_bfloat16* src =
                (mat < 2) ? (mat ? Alo : Ahi) : ((mat == 2) ? Bhi : Blo);
            const int rowbase = (mat < 2) ? m0 : n0;
            const void* g = src + (size_t)(rowbase + r) * DMODEL + k0 + c * 8;
            const uint32_t s = sb + buf * STAGEB + mat * TILEB + r * ROWB + c * 16;
            cp_async16(s, g);
        }
        CP_COMMIT();
    };

    float acc[2][8][4];
#pragma unroll
    for (int mt = 0; mt < 2; mt++)
#pragma unroll
        for (int nt = 0; nt < 8; nt++)
#pragma unroll
            for (int q = 0; q < 4; q++) acc[mt][nt][q] = 0.f;

    issue_stage(0, 0);

    for (int ch = 0; ch < 16; ch++) {
        const int buf = ch & 1;
        if (ch < 15) {
            issue_stage(ch + 1, buf ^ 1);
            CP_WAIT(1);
        } else {
            CP_WAIT(0);
        }
        __syncthreads();

        const uint32_t base = sb + buf * STAGEB;
        const int rlo = lane & 15;        // row within 16-row ldmatrix tile
        const int khalf = (lane >> 4) * 16; // byte offset for k half

#pragma unroll
        for (int ks = 0; ks < 4; ks++) {
            uint32_t ahi[2][4], alo[2][4];
#pragma unroll
            for (int mt = 0; mt < 2; mt++) {
                const uint32_t a = base + (wm + mt * 16 + rlo) * ROWB + ks * 32 + khalf;
                ldsm4(ahi[mt], a);
                ldsm4(alo[mt], a + TILEB);
            }
            uint32_t bhi[4][4], blo[4][4];
#pragma unroll
            for (int nb = 0; nb < 4; nb++) {
                const uint32_t a = base + 2 * TILEB +
                                   (wn + nb * 16 + rlo) * ROWB + ks * 32 + khalf;
                ldsm4(bhi[nb], a);
                ldsm4(blo[nb], a + TILEB);
            }
#pragma unroll
            for (int mt = 0; mt < 2; mt++)
#pragma unroll
                for (int nt = 0; nt < 8; nt++) {
                    const int nb = nt >> 1, hh = nt & 1;
                    mma16816(acc[mt][nt], ahi[mt], bhi[nb][hh], bhi[nb][2 + hh]);
                    mma16816(acc[mt][nt], ahi[mt], blo[nb][hh], blo[nb][2 + hh]);
                    mma16816(acc[mt][nt], alo[mt], bhi[nb][hh], bhi[nb][2 + hh]);
                }
        }
        __syncthreads();
    }

    // --- epilogue: fragment rows grp/grp+8, cols t4*2, t4*2+1 ---
    const int grp = lane >> 2, t4 = lane & 3;
#pragma unroll
    for (int mt = 0; mt < 2; mt++) {
#pragma unroll
        for (int h2 = 0; h2 < 2; h2++) {
            const int m = m0 + wm + mt * 16 + grp + h2 * 8;
#pragma unroll
            for (int nt = 0; nt < 8; nt++) {
                const int n = n0 + wn + nt * 8 + t4 * 2;
                float2 v;
                v.x = acc[mt][nt][h2 * 2 + 0] + bias[n];
                v.y = acc[mt][nt][h2 * 2 + 1] + bias[n + 1];
                if (HEADED) {
                    const int b  = m >> 11;
                    const int s  = m & (SEQ - 1);
                    const int h  = n >> 6;
                    const int dk = n & (HDIM - 1);
                    *(float2*)&Y[(((size_t)(b * NHEAD + h)) * SEQ + s) * HDIM + dk] = v;
                } else {
                    *(float2*)&Y[(size_t)m * DMODEL + n] = v;
                }
            }
        }
    }
}

// ============================================================================
// Causal flash attention (SIMT fp32) — unchanged (738us known good)
// ============================================================================
#define FLASH_SMEM ((64*64 + 64*65 + 64*65) * 4)

__global__ __launch_bounds__(256)
void flash_attn(const float* __restrict__ gQ, const float* __restrict__ gK,
                const float* __restrict__ gV, float* __restrict__ gO)
{
    extern __shared__ float sm[];
    float* Qs = sm;
    float* Ks = sm + 64*64;
    float* Vs = Ks + 64*65;

    const int tid = threadIdx.x;
    const int tx  = tid & 15;
    const int ty  = tid >> 4;
    const int qt  = blockIdx.x;
    const int bh  = blockIdx.y;
    const int bb  = bh >> 4;
    const int hh  = bh & 15;

    const float* Qbase = gQ + (size_t)bh * SEQ * HDIM + (size_t)qt * 64 * HDIM;
    const float* Kbh   = gK + (size_t)bh * SEQ * HDIM;
    const float* Vbh   = gV + (size_t)bh * SEQ * HDIM;

#pragma unroll
    for (int it = 0; it < 4; it++) {
        const int idx = tid + it * 256;
        const int row = idx >> 4;
        const int c4  = idx & 15;
        *(float4*)(Qs + row*64 + c4*4) = *(const float4*)(Qbase + row*64 + c4*4);
    }

    float m_i[4], l_i[4], acc[4][4];
#pragma unroll
    for (int i = 0; i < 4; i++) {
        m_i[i] = -CUDART_INF_F;
        l_i[i] = 0.f;
#pragma unroll
        for (int j = 0; j < 4; j++) acc[i][j] = 0.f;
    }

    for (int jt = 0; jt <= qt; jt++) {
        const float* Kb = Kbh + (size_t)jt * 64 * HDIM;
        const float* Vb = Vbh + (size_t)jt * 64 * HDIM;
        __syncthreads();
#pragma unroll
        for (int it = 0; it < 4; it++) {
            const int idx = tid + it * 256;
            const int row = idx >> 4;
            const int c4  = idx & 15;
            float4 kv = *(const float4*)(Kb + row*64 + c4*4);
            float4 vv = *(const float4*)(Vb + row*64 + c4*4);
            Ks[row*65 + c4*4+0] = kv.x; Ks[row*65 + c4*4+1] = kv.y;
            Ks[row*65 + c4*4+2] = kv.z; Ks[row*65 + c4*4+3] = kv.w;
            Vs[row*65 + c4*4+0] = vv.x; Vs[row*65 + c4*4+1] = vv.y;
            Vs[row*65 + c4*4+2] = vv.z; Vs[row*65 + c4*4+3] = vv.w;
        }
        __syncthreads();

        float s[4][4];
#pragma unroll
        for (int i = 0; i < 4; i++)
#pragma unroll
            for (int j = 0; j < 4; j++) s[i][j] = 0.f;

#pragma unroll 8
        for (int kk = 0; kk < HDIM; kk++) {
            float a[4], b[4];
#pragma unroll
            for (int i = 0; i < 4; i++) a[i] = Qs[(ty*4+i)*64 + kk];
#pragma unroll
            for (int j = 0; j < 4; j++) b[j] = Ks[(tx*4+j)*65 + kk];
#pragma unroll
            for (int i = 0; i < 4; i++)
#pragma unroll
                for (int j = 0; j < 4; j++)
                    s[i][j] += a[i] * b[j];
        }

        const bool diag = (jt == qt);
#pragma unroll
        for (int i = 0; i < 4; i++)
#pragma unroll
            for (int j = 0; j < 4; j++) {
                s[i][j] *= 0.125f;
                if (diag && (tx*4+j) > (ty*4+i)) s[i][j] = -1e9f;
            }

        __syncthreads();

        float p[4][4];
#pragma unroll
        for (int i = 0; i < 4; i++) {
            float t = fmaxf(fmaxf(s[i][0], s[i][1]), fmaxf(s[i][2], s[i][3]));
            t = fmaxf(t, __shfl_xor_sync(0xffffffffu, t, 8));
            t = fmaxf(t, __shfl_xor_sync(0xffffffffu, t, 4));
            t = fmaxf(t, __shfl_xor_sync(0xffffffffu, t, 2));
            t = fmaxf(t, __shfl_xor_sync(0xffffffffu, t, 1));
            const float mnew = fmaxf(m_i[i], t);
            const float corr = __expf(m_i[i] - mnew);
            float rs = 0.f;
#pragma unroll
            for (int j = 0; j < 4; j++) {
                p[i][j] = __expf(s[i][j] - mnew);
                rs += p[i][j];
            }
            rs += __shfl_xor_sync(0xffffffffu, rs, 8);
            rs += __shfl_xor_sync(0xffffffffu, rs, 4);
            rs += __shfl_xor_sync(0xffffffffu, rs, 2);
            rs += __shfl_xor_sync(0xffffffffu, rs, 1);
            l_i[i] = l_i[i] * corr + rs;
            m_i[i] = mnew;
#pragma unroll
            for (int j = 0; j < 4; j++) acc[i][j] *= corr;
#pragma unroll
            for (int j = 0; j < 4; j++)
                Ks[(ty*4+i)*65 + tx*4+j] = p[i][j];
        }
        __syncthreads();

#pragma unroll 8
        for (int kk = 0; kk < 64; kk++) {
            float a[4], b[4];
#pragma unroll
            for (int i = 0; i < 4; i++) a[i] = Ks[(ty*4+i)*65 + kk];
#pragma unroll
            for (int j = 0; j < 4; j++) b[j] = Vs[kk*65 + tx*4+j];
#pragma unroll
            for (int i = 0; i < 4; i++)
#pragma unroll
                for (int j = 0; j < 4; j++)
                    acc[i][j] += a[i] * b[j];
        }
    }

#pragma unroll
    for (int i = 0; i < 4; i++) {
        const float inv = 1.f / l_i[i];
        const int srow = qt*64 + ty*4 + i;
#pragma unroll
        for (int j = 0; j < 4; j++) {
            const int col = hh*64 + tx*4 + j;
            gO[((size_t)(bb*SEQ + srow))*DMODEL + col] = acc[i][j] * inv;
        }
    }
}

// ============================================================================
extern "C" void kernel_launch(void* const* d_in, const int* in_sizes, int n_in,
                              void* d_out, int out_size)
{
    (void)in_sizes; (void)n_in; (void)out_size;
    const float* q  = (const float*)d_in[0];
    const float* k  = (const float*)d_in[1];
    const float* v  = (const float*)d_in[2];
    const float* Wq = (const float*)d_in[4];
    const float* bq = (const float*)d_in[5];
    const float* Wk = (const float*)d_in[6];
    const float* bk = (const float*)d_in[7];
    const float* Wv = (const float*)d_in[8];
    const float* bv = (const float*)d_in[9];
    const float* Wo = (const float*)d_in[10];
    const float* bo = (const float*)d_in[11];
    float* out = (float*)d_out;

    float *gQ, *gK, *gV, *gO;
    __nv_bfloat16 *xhi, *xlo, *whi, *wlo;
    cudaGetSymbolAddress((void**)&gQ, g_Q);
    cudaGetSymbolAddress((void**)&gK, g_K);
    cudaGetSymbolAddress((void**)&gV, g_V);
    cudaGetSymbolAddress((void**)&gO, g_O);
    cudaGetSymbolAddress((void**)&xhi, g_Xhi);
    cudaGetSymbolAddress((void**)&xlo, g_Xlo);
    cudaGetSymbolAddress((void**)&whi, g_Whi);
    cudaGetSymbolAddress((void**)&wlo, g_Wlo);

    cudaFuncSetAttribute(flash_attn, cudaFuncAttributeMaxDynamicSharedMemorySize,
                         FLASH_SMEM);
    cudaFuncSetAttribute(gemm_tc<true>, cudaFuncAttributeMaxDynamicSharedMemorySize,
                         GEMM_SMEM);
    cudaFuncSetAttribute(gemm_tc<false>, cudaFuncAttributeMaxDynamicSharedMemorySize,
                         GEMM_SMEM);

    const dim3 tb(256);
    const dim3 gridG(DMODEL/128, MTOT/128);     // (8, 32)
    const int nX4 = MTOT*DMODEL/4, nW4 = DMODEL*DMODEL/4;

    // Q projection
    split_bf16<<<nX4/256, tb>>>(q,  xhi, xlo, nX4);
    split_bf16<<<nW4/256, tb>>>(Wq, whi, wlo, nW4);
    gemm_tc<true><<<gridG, tb, GEMM_SMEM>>>(xhi, xlo, whi, wlo, bq, gQ);
    // K projection
    split_bf16<<<nX4/256, tb>>>(k,  xhi, xlo, nX4);
    split_bf16<<<nW4/256, tb>>>(Wk, whi, wlo, nW4);
    gemm_tc<true><<<gridG, tb, GEMM_SMEM>>>(xhi, xlo, whi, wlo, bk, gK);
    // V projection
    split_bf16<<<nX4/256, tb>>>(v,  xhi, xlo, nX4);
    split_bf16<<<nW4/256, tb>>>(Wv, whi, wlo, nW4);
    gemm_tc<true><<<gridG, tb, GEMM_SMEM>>>(xhi, xlo, whi, wlo, bv, gV);

    // attention
    flash_attn<<<dim3(SEQ/64, BATCH*NHEAD), tb, FLASH_SMEM>>>(gQ, gK, gV, gO);

    // output projection
    split_bf16<<<nX4/256, tb>>>(gO, xhi, xlo, nX4);
    split_bf16<<<nW4/256, tb>>>(Wo, whi, wlo, nW4);
    gemm_tc<false><<<gridG, tb, GEMM_SMEM>>>(xhi, xlo, whi, wlo, bo, out);
}

// round 4
// speedup vs baseline: 2.8961x; 1.7828x over previous
#include <cuda_runtime.h>
#include <cuda_bf16.h>
#include <math_constants.h>
#include <cstdint>

// Problem constants
#define BATCH  2
#define SEQ    2048
#define DMODEL 1024
#define NHEAD  16
#define HDIM   64
#define MTOT   (BATCH*SEQ)   // 4096

// ---------------- scratch (device globals; no allocation allowed) ----------
__device__ __align__(16) __nv_bfloat16 g_Qhi[BATCH*NHEAD*SEQ*HDIM];
__device__ __align__(16) __nv_bfloat16 g_Qlo[BATCH*NHEAD*SEQ*HDIM];
__device__ __align__(16) __nv_bfloat16 g_Khi[BATCH*NHEAD*SEQ*HDIM];
__device__ __align__(16) __nv_bfloat16 g_Klo[BATCH*NHEAD*SEQ*HDIM];
__device__ __align__(16) __nv_bfloat16 g_Vhi[BATCH*NHEAD*SEQ*HDIM];
__device__ __align__(16) __nv_bfloat16 g_Vlo[BATCH*NHEAD*SEQ*HDIM];
__device__ __align__(16) __nv_bfloat16 g_Ohi[MTOT*DMODEL];
__device__ __align__(16) __nv_bfloat16 g_Olo[MTOT*DMODEL];
__device__ __align__(16) __nv_bfloat16 g_Xhi[MTOT*DMODEL];
__device__ __align__(16) __nv_bfloat16 g_Xlo[MTOT*DMODEL];
__device__ __align__(16) __nv_bfloat16 g_Whi[DMODEL*DMODEL];
__device__ __align__(16) __nv_bfloat16 g_Wlo[DMODEL*DMODEL];

// ---------------- base-PTX helpers (compute_103-safe) ----------------------
__device__ __forceinline__ uint32_t smem_u32(const void* p) {
    uint32_t a;
    asm("{ .reg .u64 t; cvta.to.shared.u64 t, %1; cvt.u32.u64 %0, t; }"
        : "=r"(a) : "l"(p));
    return a;
}
__device__ __forceinline__ void cp_async16(uint32_t s, const void* g) {
    asm volatile("cp.async.cg.shared.global [%0], [%1], 16;"
                 :: "r"(s), "l"(g) : "memory");
}
#define CP_COMMIT() asm volatile("cp.async.commit_group;" ::: "memory")
#define CP_WAIT(N)  asm volatile("cp.async.wait_group %0;" :: "n"(N) : "memory")

__device__ __forceinline__ void ldsm4(uint32_t (&r)[4], uint32_t a) {
    asm volatile("ldmatrix.sync.aligned.m8n8.x4.shared.b16 {%0,%1,%2,%3}, [%4];"
                 : "=r"(r[0]), "=r"(r[1]), "=r"(r[2]), "=r"(r[3]) : "r"(a));
}
__device__ __forceinline__ void ldsm4t(uint32_t (&r)[4], uint32_t a) {
    asm volatile("ldmatrix.sync.aligned.m8n8.x4.trans.shared.b16 {%0,%1,%2,%3}, [%4];"
                 : "=r"(r[0]), "=r"(r[1]), "=r"(r[2]), "=r"(r[3]) : "r"(a));
}
__device__ __forceinline__ void mma16816(float (&d)[4], const uint32_t (&a)[4],
                                         uint32_t b0, uint32_t b1) {
    asm volatile(
        "mma.sync.aligned.m16n8k16.row.col.f32.bf16.bf16.f32 "
        "{%0,%1,%2,%3}, {%4,%5,%6,%7}, {%8,%9}, {%0,%1,%2,%3};"
        : "+f"(d[0]), "+f"(d[1]), "+f"(d[2]), "+f"(d[3])
        : "r"(a[0]), "r"(a[1]), "r"(a[2]), "r"(a[3]), "r"(b0), "r"(b1));
}
__device__ __forceinline__ uint32_t pack_hi(float x, float y, float& lx, float& ly) {
    __nv_bfloat16 hx = __float2bfloat16(x), hy = __float2bfloat16(y);
    lx = x - __bfloat162float(hx);
    ly = y - __bfloat162float(hy);
    __nv_bfloat162 p(hx, hy);
    return *(uint32_t*)&p;
}
__device__ __forceinline__ uint32_t pack2(float x, float y) {
    __nv_bfloat162 p(__float2bfloat16(x), __float2bfloat16(y));
    return *(uint32_t*)&p;
}

// ============================================================================
// Split fp32 -> bf16 hi/lo
// ============================================================================
__global__ __launch_bounds__(256)
void split_bf16(const float* __restrict__ x, __nv_bfloat16* __restrict__ hi,
                __nv_bfloat16* __restrict__ lo, int n4)
{
    int i = blockIdx.x * blockDim.x + threadIdx.x;
    if (i >= n4) return;
    float4 v = ((const float4*)x)[i];
    __nv_bfloat16 h0 = __float2bfloat16(v.x), h1 = __float2bfloat16(v.y);
    __nv_bfloat16 h2 = __float2bfloat16(v.z), h3 = __float2bfloat16(v.w);
    ((__nv_bfloat162*)hi)[i*2+0] = __nv_bfloat162(h0, h1);
    ((__nv_bfloat162*)hi)[i*2+1] = __nv_bfloat162(h2, h3);
    ((__nv_bfloat162*)lo)[i*2+0] = __nv_bfloat162(
        __float2bfloat16(v.x - __bfloat162float(h0)),
        __float2bfloat16(v.y - __bfloat162float(h1)));
    ((__nv_bfloat162*)lo)[i*2+1] = __nv_bfloat162(
        __float2bfloat16(v.z - __bfloat162float(h2)),
        __float2bfloat16(v.w - __bfloat162float(h3)));
}

// ============================================================================
// HMMA GEMM: Y[m,n] = sum_k X[m,k]*W[n,k] + bias[n], fp32 via bf16x3.
// OMODE 0: write f32 flat [M,N].  OMODE 1: write bf16 hi/lo in [B,H,S,DK].
// ============================================================================
#define ROWB   144
#define TILEB  (128*ROWB)
#define STAGEB (4*TILEB)
#define GEMM_SMEM (2*STAGEB)       // 147456

template<int OMODE>
__global__ __launch_bounds__(256, 1)
void gemm_tc(const __nv_bfloat16* __restrict__ Ahi, const __nv_bfloat16* __restrict__ Alo,
             const __nv_bfloat16* __restrict__ Bhi, const __nv_bfloat16* __restrict__ Blo,
             const float* __restrict__ bias, float* __restrict__ Yf,
             __nv_bfloat16* __restrict__ Yhi, __nv_bfloat16* __restrict__ Ylo)
{
    extern __shared__ char smem[];
    const uint32_t sb = smem_u32(smem);
    const int tid  = threadIdx.x;
    const int wid  = tid >> 5;
    const int lane = tid & 31;
    const int n0 = blockIdx.x * 128;
    const int m0 = blockIdx.y * 128;
    const int wm = (wid & 3) * 32;
    const int wn = (wid >> 2) * 64;

    auto issue_stage = [&](int ch, int buf) {
        const int k0 = ch * 64;
#pragma unroll
        for (int i = 0; i < 16; i++) {
            const int idx = tid + i * 256;
            const int mat = idx >> 10;
            const int r   = (idx >> 3) & 127;
            const int c   = idx & 7;
            const __nv_bfloat16* src =
                (mat < 2) ? (mat ? Alo : Ahi) : ((mat == 2) ? Bhi : Blo);
            const int rowbase = (mat < 2) ? m0 : n0;
            const void* g = src + (size_t)(rowbase + r) * DMODEL + k0 + c * 8;
            cp_async16(sb + buf * STAGEB + mat * TILEB + r * ROWB + c * 16, g);
        }
        CP_COMMIT();
    };

    float acc[2][8][4];
#pragma unroll
    for (int mt = 0; mt < 2; mt++)
#pragma unroll
        for (int nt = 0; nt < 8; nt++)
#pragma unroll
            for (int q = 0; q < 4; q++) acc[mt][nt][q] = 0.f;

    issue_stage(0, 0);

    for (int ch = 0; ch < 16; ch++) {
        const int buf = ch & 1;
        if (ch < 15) { issue_stage(ch + 1, buf ^ 1); CP_WAIT(1); }
        else CP_WAIT(0);
        __syncthreads();

        const uint32_t base = sb + buf * STAGEB;
        const int rlo = lane & 15;
        const int khalf = (lane >> 4) * 16;

#pragma unroll
        for (int ks = 0; ks < 4; ks++) {
            uint32_t ahi[2][4], alo[2][4];
#pragma unroll
            for (int mt = 0; mt < 2; mt++) {
                const uint32_t a = base + (wm + mt * 16 + rlo) * ROWB + ks * 32 + khalf;
                ldsm4(ahi[mt], a);
                ldsm4(alo[mt], a + TILEB);
            }
            uint32_t bhi[4][4], blo[4][4];
#pragma unroll
            for (int nb = 0; nb < 4; nb++) {
                const uint32_t a = base + 2 * TILEB +
                                   (wn + nb * 16 + rlo) * ROWB + ks * 32 + khalf;
                ldsm4(bhi[nb], a);
                ldsm4(blo[nb], a + TILEB);
            }
#pragma unroll
            for (int mt = 0; mt < 2; mt++)
#pragma unroll
                for (int nt = 0; nt < 8; nt++) {
                    const int nb = nt >> 1, sel = nt & 1;
                    mma16816(acc[mt][nt], ahi[mt], bhi[nb][sel], bhi[nb][2 + sel]);
                    mma16816(acc[mt][nt], ahi[mt], blo[nb][sel], blo[nb][2 + sel]);
                    mma16816(acc[mt][nt], alo[mt], bhi[nb][sel], bhi[nb][2 + sel]);
                }
        }
        __syncthreads();
    }

    const int grp = lane >> 2, t4 = lane & 3;
#pragma unroll
    for (int mt = 0; mt < 2; mt++) {
#pragma unroll
        for (int h2 = 0; h2 < 2; h2++) {
            const int m = m0 + wm + mt * 16 + grp + h2 * 8;
#pragma unroll
            for (int nt = 0; nt < 8; nt++) {
                const int n = n0 + wn + nt * 8 + t4 * 2;
                const float v0 = acc[mt][nt][h2 * 2 + 0] + bias[n];
                const float v1 = acc[mt][nt][h2 * 2 + 1] + bias[n + 1];
                if (OMODE == 0) {
                    float2 v; v.x = v0; v.y = v1;
                    *(float2*)&Yf[(size_t)m * DMODEL + n] = v;
                } else {
                    const int b  = m >> 11;
                    const int s  = m & (SEQ - 1);
                    const int h  = n >> 6;
                    const int dk = n & (HDIM - 1);
                    const size_t o = (((size_t)(b * NHEAD + h)) * SEQ + s) * HDIM + dk;
                    float l0, l1;
                    const uint32_t hp = pack_hi(v0, v1, l0, l1);
                    *(uint32_t*)&Yhi[o] = hp;
                    *(uint32_t*)&Ylo[o] = pack2(l0, l1);
                }
            }
        }
    }
}

// ============================================================================
// HMMA causal flash attention, bf16x3 precision.
// CTA: 128 q-rows of one (b,h), 256 threads (8 warps x 16 rows). K/V tiles 64.
// ============================================================================
#define F_QLO   (128*144)            // 18432 (Qhi size)
#define F_STG   (2*128*144)          // 36864
#define F_TILE  (64*144)             // 9216
#define F_STAGEB (4*F_TILE)          // 36864
#define FLASH_SMEM (F_STG + 2*F_STAGEB)  // 110592

__global__ __launch_bounds__(256, 1)
void flash_hmma(const __nv_bfloat16* __restrict__ Qhi_, const __nv_bfloat16* __restrict__ Qlo_,
                const __nv_bfloat16* __restrict__ Khi_, const __nv_bfloat16* __restrict__ Klo_,
                const __nv_bfloat16* __restrict__ Vhi_, const __nv_bfloat16* __restrict__ Vlo_,
                __nv_bfloat16* __restrict__ Ohi_, __nv_bfloat16* __restrict__ Olo_)
{
    extern __shared__ char smem[];
    const uint32_t sb = smem_u32(smem);
    const int tid = threadIdx.x, wid = tid >> 5, lane = tid & 31;
    const int qt = (int)(gridDim.x - 1) - (int)blockIdx.x;   // heavy tiles first
    const int bh = blockIdx.y;
    const int bb = bh >> 4, hd = bh & 15;
    const int wq = wid * 16;
    const int grp = lane >> 2, t4 = lane & 3;
    const int qbase = qt * 128;
    const size_t bhoff = (size_t)bh * SEQ * HDIM;

    // Q stage (group 0)
#pragma unroll
    for (int i = 0; i < 8; i++) {
        const int idx = tid + i * 256;           // 0..2047
        const int mat = idx >> 10;               // 0..1
        const int r = (idx >> 3) & 127, c = idx & 7;
        const __nv_bfloat16* src = (mat ? Qlo_ : Qhi_) + bhoff +
                                   (size_t)(qbase + r) * HDIM + c * 8;
        cp_async16(sb + mat * F_QLO + r * 144 + c * 16, src);
    }
    CP_COMMIT();

    const int njt = 2 * (qt + 1);
    auto issue_kv = [&](int jt, int buf) {
        const int k0 = jt * 64;
#pragma unroll
        for (int i = 0; i < 8; i++) {
            const int idx = tid + i * 256;       // 0..2047
            const int mat = idx >> 9;            // 0:Khi 1:Klo 2:Vhi 3:Vlo
            const int r = (idx >> 3) & 63, c = idx & 7;
            const __nv_bfloat16* src = (mat == 0) ? Khi_ : (mat == 1) ? Klo_
                                     : (mat == 2) ? Vhi_ : Vlo_;
            const void* g = src + bhoff + (size_t)(k0 + r) * HDIM + c * 8;
            cp_async16(sb + F_STG + buf * F_STAGEB + mat * F_TILE + r * 144 + c * 16, g);
        }
        CP_COMMIT();
    };
    issue_kv(0, 0);

    CP_WAIT(1);            // Q done (stage0 may be pending)
    __syncthreads();

    // Q fragments -> registers
    const int rlo = lane & 15;
    const int khalf = (lane >> 4) * 16;
    uint32_t qh[4][4], ql[4][4];
#pragma unroll
    for (int ks = 0; ks < 4; ks++) {
        const uint32_t a = sb + (wq + rlo) * 144 + ks * 32 + khalf;
        ldsm4(qh[ks], a);
        ldsm4(ql[ks], a + F_QLO);
    }

    float mr0 = -CUDART_INF_F, mr1 = -CUDART_INF_F, lr0 = 0.f, lr1 = 0.f;
    float out[8][4];
#pragma unroll
    for (int nf = 0; nf < 8; nf++)
#pragma unroll
        for (int q = 0; q < 4; q++) out[nf][q] = 0.f;

    const int r0g = qbase + wq + grp;       // global q row (first)
    const int r1g = r0g + 8;

    for (int jt = 0; jt < njt; jt++) {
        const int buf = jt & 1;
        if (jt + 1 < njt) { issue_kv(jt + 1, buf ^ 1); CP_WAIT(1); }
        else CP_WAIT(0);
        __syncthreads();
        const uint32_t kb = sb + F_STG + buf * F_STAGEB;

        // ---- S = Q K^T (bf16x3) ----
        float s[8][4];
#pragma unroll
        for (int nf = 0; nf < 8; nf++)
#pragma unroll
            for (int q = 0; q < 4; q++) s[nf][q] = 0.f;

#pragma unroll
        for (int ks = 0; ks < 4; ks++) {
            uint32_t kh[4][4], kl[4][4];
#pragma unroll
            for (int nb = 0; nb < 4; nb++) {
                const uint32_t a = kb + (nb * 16 + rlo) * 144 + ks * 32 + khalf;
                ldsm4(kh[nb], a);
                ldsm4(kl[nb], a + F_TILE);
            }
#pragma unroll
            for (int nf = 0; nf < 8; nf++) {
                const int nb = nf >> 1, sel = nf & 1;
                mma16816(s[nf], qh[ks], kh[nb][sel], kh[nb][2 + sel]);
                mma16816(s[nf], qh[ks], kl[nb][sel], kl[nb][2 + sel]);
                mma16816(s[nf], ql[ks], kh[nb][sel], kh[nb][2 + sel]);
            }
        }

        // ---- scale + causal mask ----
        const int k0 = jt * 64;
        const bool maskt = (jt >= njt - 2);
#pragma unroll
        for (int nf = 0; nf < 8; nf++) {
#pragma unroll
            for (int q = 0; q < 4; q++) s[nf][q] *= 0.125f;
            if (maskt) {
                const int c0 = k0 + nf * 8 + t4 * 2, c1 = c0 + 1;
                if (c0 > r0g) s[nf][0] = -1e9f;
                if (c1 > r0g) s[nf][1] = -1e9f;
                if (c0 > r1g) s[nf][2] = -1e9f;
                if (c1 > r1g) s[nf][3] = -1e9f;
            }
        }

        // ---- online softmax ----
        float mx0 = -CUDART_INF_F, mx1 = -CUDART_INF_F;
#pragma unroll
        for (int nf = 0; nf < 8; nf++) {
            mx0 = fmaxf(mx0, fmaxf(s[nf][0], s[nf][1]));
            mx1 = fmaxf(mx1, fmaxf(s[nf][2], s[nf][3]));
        }
        mx0 = fmaxf(mx0, __shfl_xor_sync(0xffffffffu, mx0, 1));
        mx0 = fmaxf(mx0, __shfl_xor_sync(0xffffffffu, mx0, 2));
        mx1 = fmaxf(mx1, __shfl_xor_sync(0xffffffffu, mx1, 1));
        mx1 = fmaxf(mx1, __shfl_xor_sync(0xffffffffu, mx1, 2));
        const float mn0 = fmaxf(mr0, mx0), mn1 = fmaxf(mr1, mx1);
        const float cr0 = __expf(mr0 - mn0), cr1 = __expf(mr1 - mn1);
        float sum0 = 0.f, sum1 = 0.f;
#pragma unroll
        for (int nf = 0; nf < 8; nf++) {
            s[nf][0] = __expf(s[nf][0] - mn0); sum0 += s[nf][0];
            s[nf][1] = __expf(s[nf][1] - mn0); sum0 += s[nf][1];
            s[nf][2] = __expf(s[nf][2] - mn1); sum1 += s[nf][2];
            s[nf][3] = __expf(s[nf][3] - mn1); sum1 += s[nf][3];
        }
        sum0 += __shfl_xor_sync(0xffffffffu, sum0, 1);
        sum0 += __shfl_xor_sync(0xffffffffu, sum0, 2);
        sum1 += __shfl_xor_sync(0xffffffffu, sum1, 1);
        sum1 += __shfl_xor_sync(0xffffffffu, sum1, 2);
        lr0 = lr0 * cr0 + sum0;
        lr1 = lr1 * cr1 + sum1;
        mr0 = mn0; mr1 = mn1;
#pragma unroll
        for (int nf = 0; nf < 8; nf++) {
            out[nf][0] *= cr0; out[nf][1] *= cr0;
            out[nf][2] *= cr1; out[nf][3] *= cr1;
        }

        // ---- O += P V (bf16x3) ----
        const int vrow = (lane & 7) + ((lane >> 4) << 3);
        const int vcol = (lane & 8);
#pragma unroll
        for (int ks = 0; ks < 4; ks++) {
            uint32_t ph[4], pl[4];
            {
                float l0, l1;
                ph[0] = pack_hi(s[2*ks][0],   s[2*ks][1],   l0, l1); pl[0] = pack2(l0, l1);
                ph[1] = pack_hi(s[2*ks][2],   s[2*ks][3],   l0, l1); pl[1] = pack2(l0, l1);
                ph[2] = pack_hi(s[2*ks+1][0], s[2*ks+1][1], l0, l1); pl[2] = pack2(l0, l1);
                ph[3] = pack_hi(s[2*ks+1][2], s[2*ks+1][3], l0, l1); pl[3] = pack2(l0, l1);
            }
#pragma unroll
            for (int nb = 0; nb < 4; nb++) {
                uint32_t vh[4], vl[4];
                const uint32_t a = kb + 2 * F_TILE + (ks * 16 + vrow) * 144 +
                                   (nb * 16 + vcol) * 2;
                ldsm4t(vh, a);
                ldsm4t(vl, a + F_TILE);
                mma16816(out[2*nb],   ph, vh[0], vh[2]);
                mma16816(out[2*nb],   ph, vl[0], vl[2]);
                mma16816(out[2*nb],   pl, vh[0], vh[2]);
                mma16816(out[2*nb+1], ph, vh[1], vh[3]);
                mma16816(out[2*nb+1], ph, vl[1], vl[3]);
                mma16816(out[2*nb+1], pl, vh[1], vh[3]);
            }
        }
        __syncthreads();   // protect buf before next issue overwrites it
    }

    // ---- epilogue: normalize, split hi/lo, write [B,S,D] ----
    const float inv0 = 1.f / lr0, inv1 = 1.f / lr1;
    const size_t bs0 = (size_t)(bb * SEQ + qbase + wq + grp) * DMODEL;
    const size_t bs1 = bs0 + 8 * DMODEL;
#pragma unroll
    for (int nf = 0; nf < 8; nf++) {
        const int col = hd * 64 + nf * 8 + t4 * 2;
        float l0, l1;
        uint32_t hp = pack_hi(out[nf][0] * inv0, out[nf][1] * inv0, l0, l1);
        *(uint32_t*)&Ohi_[bs0 + col] = hp;
        *(uint32_t*)&Olo_[bs0 + col] = pack2(l0, l1);
        hp = pack_hi(out[nf][2] * inv1, out[nf][3] * inv1, l0, l1);
        *(uint32_t*)&Ohi_[bs1 + col] = hp;
        *(uint32_t*)&Olo_[bs1 + col] = pack2(l0, l1);
    }
}

// ============================================================================
extern "C" void kernel_launch(void* const* d_in, const int* in_sizes, int n_in,
                              void* d_out, int out_size)
{
    (void)in_sizes; (void)n_in; (void)out_size;
    const float* q  = (const float*)d_in[0];
    const float* k  = (const float*)d_in[1];
    const float* v  = (const float*)d_in[2];
    const float* Wq = (const float*)d_in[4];
    const float* bq = (const float*)d_in[5];
    const float* Wk = (const float*)d_in[6];
    const float* bk = (const float*)d_in[7];
    const float* Wv = (const float*)d_in[8];
    const float* bv = (const float*)d_in[9];
    const float* Wo = (const float*)d_in[10];
    const float* bo = (const float*)d_in[11];
    float* out = (float*)d_out;

    __nv_bfloat16 *qhi, *qlo, *khi, *klo, *vhi, *vlo, *ohi, *olo, *xhi, *xlo, *whi, *wlo;
    cudaGetSymbolAddress((void**)&qhi, g_Qhi);
    cudaGetSymbolAddress((void**)&qlo, g_Qlo);
    cudaGetSymbolAddress((void**)&khi, g_Khi);
    cudaGetSymbolAddress((void**)&klo, g_Klo);
    cudaGetSymbolAddress((void**)&vhi, g_Vhi);
    cudaGetSymbolAddress((void**)&vlo, g_Vlo);
    cudaGetSymbolAddress((void**)&ohi, g_Ohi);
    cudaGetSymbolAddress((void**)&olo, g_Olo);
    cudaGetSymbolAddress((void**)&xhi, g_Xhi);
    cudaGetSymbolAddress((void**)&xlo, g_Xlo);
    cudaGetSymbolAddress((void**)&whi, g_Whi);
    cudaGetSymbolAddress((void**)&wlo, g_Wlo);

    cudaFuncSetAttribute(gemm_tc<0>, cudaFuncAttributeMaxDynamicSharedMemorySize, GEMM_SMEM);
    cudaFuncSetAttribute(gemm_tc<1>, cudaFuncAttributeMaxDynamicSharedMemorySize, GEMM_SMEM);
    cudaFuncSetAttribute(flash_hmma, cudaFuncAttributeMaxDynamicSharedMemorySize, FLASH_SMEM);

    const dim3 tb(256);
    const dim3 gridG(DMODEL/128, MTOT/128);     // (8, 32)
    const int nX4 = MTOT*DMODEL/4, nW4 = DMODEL*DMODEL/4;

    // Q projection
    split_bf16<<<nX4/256, tb>>>(q,  xhi, xlo, nX4);
    split_bf16<<<nW4/256, tb>>>(Wq, whi, wlo, nW4);
    gemm_tc<1><<<gridG, tb, GEMM_SMEM>>>(xhi, xlo, whi, wlo, bq, nullptr, qhi, qlo);
    // K projection
    split_bf16<<<nX4/256, tb>>>(k,  xhi, xlo, nX4);
    split_bf16<<<nW4/256, tb>>>(Wk, whi, wlo, nW4);
    gemm_tc<1><<<gridG, tb, GEMM_SMEM>>>(xhi, xlo, whi, wlo, bk, nullptr, khi, klo);
    // V projection
    split_bf16<<<nX4/256, tb>>>(v,  xhi, xlo, nX4);
    split_bf16<<<nW4/256, tb>>>(Wv, whi, wlo, nW4);
    gemm_tc<1><<<gridG, tb, GEMM_SMEM>>>(xhi, xlo, whi, wlo, bv, nullptr, vhi, vlo);

    // attention (HMMA)
    flash_hmma<<<dim3(SEQ/128, BATCH*NHEAD), tb, FLASH_SMEM>>>(
        qhi, qlo, khi, klo, vhi, vlo, ohi, olo);

    // output projection
    split_bf16<<<nW4/256, tb>>>(Wo, whi, wlo, nW4);
    gemm_tc<0><<<gridG, tb, GEMM_SMEM>>>(ohi, olo, whi, wlo, bo, out, nullptr, nullptr);
}